// round 10
// baseline (speedup 1.0000x reference)
#include <cuda_runtime.h>
#include <cuda_fp16.h>
#include <math.h>

#define H_IN   14
#define W_IN   14
#define HP     12
#define WP     12
#define ISZ    144
#define OSZ    16
#define NPOS   1152
#define VSH2   136         // votes stride per i, in half2 units (272 halfs = 544 B)
#define RST    145         // rp/z row stride (floats): odd -> conflict-free columns
#define EPSF   1e-9f

struct Smem {
    __half2 votes[ISZ * VSH2];    // [i][o*8 + pp]   78336 B
    float poseS[ISZ * 16];        //                  9216 B
    float actS[ISZ];              //                   576 B
    float rpT[OSZ * RST];         // [o][i] rr*act    9280 B
    float zS[OSZ * RST];          // [o][i] log-lik   9280 B
};                                 // total 106688 B -> 2 CTAs/SM

__global__ void __launch_bounds__(512, 2)
capsconv_em_kernel(const float* __restrict__ pose_in,   // [8,14,14,256]
                   const float* __restrict__ act_in,    // [8,14,14,16]
                   const float* __restrict__ w,         // [144,16,16]
                   const float* __restrict__ beta_v,    // [16]
                   const float* __restrict__ beta_a,    // [16]
                   float* __restrict__ out)             // pose[1152*256] ++ act[1152*16]
{
    extern __shared__ char smem_raw[];
    Smem& sm = *reinterpret_cast<Smem*>(smem_raw);

    const int tid = threadIdx.x;
    const int n   = blockIdx.x;
    const int b   = n / (HP * WP);
    const int rem = n % (HP * WP);
    const int y   = rem / WP;
    const int x   = rem % WP;

    // ---- Stage pose patch + activations (coalesced) ----
    for (int idx = tid; idx < ISZ * 4; idx += 512) {
        int i  = idx >> 2;
        int p4 = idx & 3;
        int pos = i >> 4, cc = i & 15;
        int ky = pos / 3, kx = pos % 3;
        const float4* src = reinterpret_cast<const float4*>(
            pose_in + ((((b * H_IN) + y + ky) * W_IN + (x + kx)) * 256 + cc * 16));
        reinterpret_cast<float4*>(sm.poseS)[i * 4 + p4] = src[p4];
    }
    for (int i = tid; i < ISZ; i += 512) {
        int pos = i >> 4, cc = i & 15;
        int ky = pos / 3, kx = pos % 3;
        sm.actS[i] = act_in[(((b * H_IN) + y + ky) * W_IN + (x + kx)) * OSZ + cc];
    }
    __syncthreads();

    // ---- rp init (iteration 0: rr uniform) ----
    for (int idx = tid; idx < OSZ * ISZ; idx += 512) {
        int oo = idx / ISZ;
        int i  = idx - oo * ISZ;
        sm.rpT[oo * RST + i] = sm.actS[i] * 0.0625f;
    }

    // ---- Vote transform: votes[i][o][pr,:] = pose[i][pr,:] @ w[i][o], fp16 store ----
    for (int pair = tid; pair < ISZ * OSZ; pair += 512) {
        int i  = pair >> 4;
        int oo = pair & 15;
        const float4* wrow = reinterpret_cast<const float4*>(w + pair * 16);
        float4 w0 = wrow[0], w1 = wrow[1], w2 = wrow[2], w3 = wrow[3];
        const float* ps = sm.poseS + i * 16;
        #pragma unroll
        for (int pr = 0; pr < 4; pr++) {
            float a0 = ps[pr * 4 + 0], a1 = ps[pr * 4 + 1];
            float a2 = ps[pr * 4 + 2], a3 = ps[pr * 4 + 3];
            float rx = fmaf(a0, w0.x, fmaf(a1, w1.x, fmaf(a2, w2.x, a3 * w3.x)));
            float ry = fmaf(a0, w0.y, fmaf(a1, w1.y, fmaf(a2, w2.y, a3 * w3.y)));
            float rz = fmaf(a0, w0.z, fmaf(a1, w1.z, fmaf(a2, w2.z, a3 * w3.z)));
            float rw = fmaf(a0, w0.w, fmaf(a1, w1.w, fmaf(a2, w2.w, a3 * w3.w)));
            __half2 h0 = __float22half2_rn(make_float2(rx, ry));
            __half2 h1 = __float22half2_rn(make_float2(rz, rw));
            uint2 st;
            st.x = *reinterpret_cast<unsigned int*>(&h0);
            st.y = *reinterpret_cast<unsigned int*>(&h1);
            *reinterpret_cast<uint2*>(sm.votes + i * VSH2 + oo * 8 + pr * 2) = st;
        }
    }

    // ---- EM mapping: warp <-> o ; lane = c*4 + pg ; i = c + 8*ii ----
    const int lane = tid & 31;
    const int o    = tid >> 5;
    const int pg   = lane & 3;      // this lane's 4 p dims: [4pg, 4pg+4)
    const int c    = lane >> 2;     // i-chunk
    const float bv = beta_v[o];
    const float ba = beta_a[o];
    const __half2* vbase = sm.votes + o * 8 + pg * 2;
    const float* rpo = sm.rpT + o * RST;
    __syncthreads();   // rp + votes ready

    // ---- Iterations 0,1: fp16 M-step + E-step ----
    for (int it = 0; it < 2; ++it) {
        float m0=0.f,m1=0.f,m2=0.f,m3=0.f;
        float s0=0.f,s1=0.f,s2=0.f,s3=0.f;
        float rs=0.f;
        #pragma unroll 6
        for (int ii = 0; ii < 18; ++ii) {
            const int i = c + (ii << 3);
            float rp = rpo[i];
            uint2 hv = *reinterpret_cast<const uint2*>(vbase + i * VSH2);
            float2 f01 = __half22float2(*reinterpret_cast<__half2*>(&hv.x));
            float2 f23 = __half22float2(*reinterpret_cast<__half2*>(&hv.y));
            float tx = rp * f01.x, ty = rp * f01.y;
            float tz = rp * f23.x, tw = rp * f23.y;
            m0 += tx;  s0 = fmaf(tx, f01.x, s0);
            m1 += ty;  s1 = fmaf(ty, f01.y, s1);
            m2 += tz;  s2 = fmaf(tz, f23.x, s2);
            m3 += tw;  s3 = fmaf(tw, f23.y, s3);
            rs += rp;
        }
        #pragma unroll
        for (int off = 4; off < 32; off <<= 1) {
            m0 += __shfl_xor_sync(0xffffffffu, m0, off);
            m1 += __shfl_xor_sync(0xffffffffu, m1, off);
            m2 += __shfl_xor_sync(0xffffffffu, m2, off);
            m3 += __shfl_xor_sync(0xffffffffu, m3, off);
            s0 += __shfl_xor_sync(0xffffffffu, s0, off);
            s1 += __shfl_xor_sync(0xffffffffu, s1, off);
            s2 += __shfl_xor_sync(0xffffffffu, s2, off);
            s3 += __shfl_xor_sync(0xffffffffu, s3, off);
            rs += __shfl_xor_sync(0xffffffffu, rs, off);
        }
        const float inv_r = __fdividef(1.0f, rs + EPSF);
        const float me0 = m0 * inv_r, me1 = m1 * inv_r;
        const float me2 = m2 * inv_r, me3 = m3 * inv_r;
        float e0 = fmaf(me0, fmaf(me0, rs, -2.0f * m0), s0);
        float e1 = fmaf(me1, fmaf(me1, rs, -2.0f * m1), s1);
        float e2 = fmaf(me2, fmaf(me2, rs, -2.0f * m2), s2);
        float e3 = fmaf(me3, fmaf(me3, rs, -2.0f * m3), s3);
        float v0 = fmaxf(e0, 0.f) * inv_r, v1 = fmaxf(e1, 0.f) * inv_r;
        float v2 = fmaxf(e2, 0.f) * inv_r, v3 = fmaxf(e3, 0.f) * inv_r;
        float l4 = (__logf(sqrtf(v0) + EPSF) + __logf(sqrtf(v1) + EPSF))
                 + (__logf(sqrtf(v2) + EPSF) + __logf(sqrtf(v3) + EPSF));
        float lsum = l4;
        lsum += __shfl_xor_sync(0xffffffffu, lsum, 1);
        lsum += __shfl_xor_sync(0xffffffffu, lsum, 2);

        const float inv_temp = 1.0f + (float)it;
        const float cost = fmaf(16.0f, bv, lsum) * rs;
        const float a = __fdividef(1.0f, 1.0f + __expf(-inv_temp * (ba - cost)));

        const float iv0 = __fdividef(1.0f, 2.0f * v0 + EPSF);
        const float iv1 = __fdividef(1.0f, 2.0f * v1 + EPSF);
        const float iv2 = __fdividef(1.0f, 2.0f * v2 + EPSF);
        const float iv3 = __fdividef(1.0f, 2.0f * v3 + EPSF);
        const float zc  = __logf(a + EPSF) - lsum;     // z = zc - distance

        // E-step part 1: distances from this warp's own strip
        #pragma unroll 3
        for (int ii = 0; ii < 18; ++ii) {
            const int i = c + (ii << 3);
            uint2 hv = *reinterpret_cast<const uint2*>(vbase + i * VSH2);
            float2 f01 = __half22float2(*reinterpret_cast<__half2*>(&hv.x));
            float2 f23 = __half22float2(*reinterpret_cast<__half2*>(&hv.y));
            float dx = f01.x - me0, dy = f01.y - me1;
            float dz = f23.x - me2, dw = f23.y - me3;
            float acc = dx * dx * iv0;
            acc = fmaf(dy * dy, iv1, acc);
            acc = fmaf(dz * dz, iv2, acc);
            acc = fmaf(dw * dw, iv3, acc);
            acc += __shfl_xor_sync(0xffffffffu, acc, 1);
            acc += __shfl_xor_sync(0xffffffffu, acc, 2);    // sum over 16 p
            if (pg == 0)
                sm.zS[o * RST + i] = zc - acc;
        }
        __syncthreads();   // z ready

        // E-step part 2: softmax over o, fold act -> rp
        if (tid < 2 * ISZ) {
            const int i  = tid >> 1;
            const int g2 = tid & 1;
            float zz[8];
            float zmax = -1e30f;
            #pragma unroll
            for (int j = 0; j < 8; ++j) {
                float z = sm.zS[((j << 1) + g2) * RST + i];
                zz[j] = z;
                zmax = fmaxf(zmax, z);
            }
            zmax = fmaxf(zmax, __shfl_xor_sync(0xffffffffu, zmax, 1));
            float es = 0.f;
            #pragma unroll
            for (int j = 0; j < 8; ++j) { zz[j] = __expf(zz[j] - zmax); es += zz[j]; }
            es += __shfl_xor_sync(0xffffffffu, es, 1);
            const float f = __fdividef(sm.actS[i], es);   // softmax * act
            #pragma unroll
            for (int j = 0; j < 8; ++j)
                sm.rpT[((j << 1) + g2) * RST + i] = zz[j] * f;
        }
        __syncthreads();   // rp ready
    }

    // ---- Final M-step in fp32: recompute votes from poseS + w (L2-hot) ----
    {
        float m0=0.f,m1=0.f,m2=0.f,m3=0.f;
        float s0=0.f,s1=0.f,s2=0.f,s3=0.f;
        float rs=0.f;
        #pragma unroll 2
        for (int ii = 0; ii < 18; ++ii) {
            const int i = c + (ii << 3);
            float rp = rpo[i];
            float4 pv = reinterpret_cast<const float4*>(sm.poseS)[i * 4 + pg];
            const float4* wr = reinterpret_cast<const float4*>(w) + (i * 16 + o) * 4;
            float4 w0 = wr[0], w1 = wr[1], w2 = wr[2], w3 = wr[3];
            float vv0 = fmaf(pv.x, w0.x, fmaf(pv.y, w1.x, fmaf(pv.z, w2.x, pv.w * w3.x)));
            float vv1 = fmaf(pv.x, w0.y, fmaf(pv.y, w1.y, fmaf(pv.z, w2.y, pv.w * w3.y)));
            float vv2 = fmaf(pv.x, w0.z, fmaf(pv.y, w1.z, fmaf(pv.z, w2.z, pv.w * w3.z)));
            float vv3 = fmaf(pv.x, w0.w, fmaf(pv.y, w1.w, fmaf(pv.z, w2.w, pv.w * w3.w)));
            float tx = rp * vv0, ty = rp * vv1, tz = rp * vv2, tw = rp * vv3;
            m0 += tx;  s0 = fmaf(tx, vv0, s0);
            m1 += ty;  s1 = fmaf(ty, vv1, s1);
            m2 += tz;  s2 = fmaf(tz, vv2, s2);
            m3 += tw;  s3 = fmaf(tw, vv3, s3);
            rs += rp;
        }
        #pragma unroll
        for (int off = 4; off < 32; off <<= 1) {
            m0 += __shfl_xor_sync(0xffffffffu, m0, off);
            m1 += __shfl_xor_sync(0xffffffffu, m1, off);
            m2 += __shfl_xor_sync(0xffffffffu, m2, off);
            m3 += __shfl_xor_sync(0xffffffffu, m3, off);
            s0 += __shfl_xor_sync(0xffffffffu, s0, off);
            s1 += __shfl_xor_sync(0xffffffffu, s1, off);
            s2 += __shfl_xor_sync(0xffffffffu, s2, off);
            s3 += __shfl_xor_sync(0xffffffffu, s3, off);
            rs += __shfl_xor_sync(0xffffffffu, rs, off);
        }
        const float inv_r = __fdividef(1.0f, rs + EPSF);
        const float me0 = m0 * inv_r, me1 = m1 * inv_r;
        const float me2 = m2 * inv_r, me3 = m3 * inv_r;
        float e0 = fmaf(me0, fmaf(me0, rs, -2.0f * m0), s0);
        float e1 = fmaf(me1, fmaf(me1, rs, -2.0f * m1), s1);
        float e2 = fmaf(me2, fmaf(me2, rs, -2.0f * m2), s2);
        float e3 = fmaf(me3, fmaf(me3, rs, -2.0f * m3), s3);
        float v0 = fmaxf(e0, 0.f) * inv_r, v1 = fmaxf(e1, 0.f) * inv_r;
        float v2 = fmaxf(e2, 0.f) * inv_r, v3 = fmaxf(e3, 0.f) * inv_r;
        float l4 = (__logf(sqrtf(v0) + EPSF) + __logf(sqrtf(v1) + EPSF))
                 + (__logf(sqrtf(v2) + EPSF) + __logf(sqrtf(v3) + EPSF));
        float lsum = l4;
        lsum += __shfl_xor_sync(0xffffffffu, lsum, 1);
        lsum += __shfl_xor_sync(0xffffffffu, lsum, 2);

        const float cost = fmaf(16.0f, bv, lsum) * rs;
        const float a = __fdividef(1.0f, 1.0f + __expf(-3.0f * (ba - cost)));

        if (c == 0) {   // lanes 0-3: pg 0..3 -> coalesced 64B per warp
            *reinterpret_cast<float4*>(out + n * 256 + o * 16 + pg * 4) =
                make_float4(me0, me1, me2, me3);
        }
        if (lane == 0)
            out[NPOS * 256 + n * OSZ + o] = a;
    }
}

extern "C" void kernel_launch(void* const* d_in, const int* in_sizes, int n_in,
                              void* d_out, int out_size)
{
    const float* pose_in = (const float*)d_in[0];
    const float* act_in  = (const float*)d_in[1];
    const float* w       = (const float*)d_in[2];
    const float* bv      = (const float*)d_in[3];
    const float* ba      = (const float*)d_in[4];
    float* out           = (float*)d_out;

    const int smem = (int)sizeof(Smem);
    cudaFuncSetAttribute(capsconv_em_kernel,
                         cudaFuncAttributeMaxDynamicSharedMemorySize, smem);
    capsconv_em_kernel<<<NPOS, 512, smem>>>(pose_in, act_in, w, bv, ba, out);
}

// round 11
// speedup vs baseline: 1.1408x; 1.1408x over previous
#include <cuda_runtime.h>
#include <cuda_fp16.h>
#include <math.h>

#define H_IN   14
#define W_IN   14
#define HP     12
#define WP     12
#define ISZ    144
#define OSZ    16
#define NPOS   1152
#define VSH2   136         // votes stride per i in half2 units (136 words ≡ 8 mod 32)
#define RST    145         // rp/z row stride (floats): odd -> conflict-free columns
#define EPSF   1e-9f

struct Smem {
    __half2 votes[ISZ * VSH2];    // staging only: [i][o*8 + p/2]   78336 B
    float poseS[ISZ * 16];        //                                  9216 B
    float actS[ISZ];              //                                   576 B
    float rpT[OSZ * RST];         // [o][i] rr*act                    9280 B
    float zpart[2][OSZ * RST];    // [h][o][i] 8-p distance partials 18560 B
    float l8S[2][OSZ];            // [h][o] 8-p log-sigma partials     128 B
    float rsS[OSZ];               //                                    64 B
    float czS[OSZ];               // log(a)+... - lsum                  64 B
};                                 // total ~116 KB (1 CTA of 1024 thr)

__global__ void __launch_bounds__(1024, 1)
capsconv_em_kernel(const float* __restrict__ pose_in,   // [8,14,14,256]
                   const float* __restrict__ act_in,    // [8,14,14,16]
                   const float* __restrict__ w,         // [144,16,16]
                   const float* __restrict__ beta_v,    // [16]
                   const float* __restrict__ beta_a,    // [16]
                   float* __restrict__ out)             // pose[1152*256] ++ act[1152*16]
{
    extern __shared__ char smem_raw[];
    Smem& sm = *reinterpret_cast<Smem*>(smem_raw);

    const int tid = threadIdx.x;
    const int n   = blockIdx.x;
    const int b   = n / (HP * WP);
    const int rem = n % (HP * WP);
    const int y   = rem / WP;
    const int x   = rem % WP;

    // ---- Stage pose patch + activations (coalesced) ----
    for (int idx = tid; idx < ISZ * 4; idx += 1024) {
        int i  = idx >> 2;
        int p4 = idx & 3;
        int pos = i >> 4, cc = i & 15;
        int ky = pos / 3, kx = pos % 3;
        const float4* src = reinterpret_cast<const float4*>(
            pose_in + ((((b * H_IN) + y + ky) * W_IN + (x + kx)) * 256 + cc * 16));
        reinterpret_cast<float4*>(sm.poseS)[i * 4 + p4] = src[p4];
    }
    for (int i = tid; i < ISZ; i += 1024) {
        int pos = i >> 4, cc = i & 15;
        int ky = pos / 3, kx = pos % 3;
        sm.actS[i] = act_in[(((b * H_IN) + y + ky) * W_IN + (x + kx)) * OSZ + cc];
    }
    // rp init for iteration 0 (rr uniform 1/16)
    for (int idx = tid; idx < OSZ * ISZ; idx += 1024) {
        int oo = idx / ISZ;
        int i  = idx - oo * ISZ;
        sm.rpT[oo * RST + i] = 0.0625f;   // act folded below? no: rp = rr*act
    }
    __syncthreads();
    // fix: rp = act/16 (needs actS ready)
    for (int idx = tid; idx < OSZ * ISZ; idx += 1024) {
        int oo = idx / ISZ;
        int i  = idx - oo * ISZ;
        sm.rpT[oo * RST + i] = sm.actS[i] * 0.0625f;
    }

    // ---- Vote transform -> SMEM staging (fp16) ----
    for (int pair = tid; pair < ISZ * OSZ; pair += 1024) {
        int i  = pair >> 4;
        int oo = pair & 15;
        const float4* wrow = reinterpret_cast<const float4*>(w + pair * 16);
        float4 w0 = wrow[0], w1 = wrow[1], w2 = wrow[2], w3 = wrow[3];
        const float* ps = sm.poseS + i * 16;
        #pragma unroll
        for (int pr = 0; pr < 4; pr++) {
            float a0 = ps[pr * 4 + 0], a1 = ps[pr * 4 + 1];
            float a2 = ps[pr * 4 + 2], a3 = ps[pr * 4 + 3];
            float rx = fmaf(a0, w0.x, fmaf(a1, w1.x, fmaf(a2, w2.x, a3 * w3.x)));
            float ry = fmaf(a0, w0.y, fmaf(a1, w1.y, fmaf(a2, w2.y, a3 * w3.y)));
            float rz = fmaf(a0, w0.z, fmaf(a1, w1.z, fmaf(a2, w2.z, a3 * w3.z)));
            float rw = fmaf(a0, w0.w, fmaf(a1, w1.w, fmaf(a2, w2.w, a3 * w3.w)));
            __half2 h0 = __float22half2_rn(make_float2(rx, ry));
            __half2 h1 = __float22half2_rn(make_float2(rz, rw));
            uint2 st;
            st.x = *reinterpret_cast<unsigned int*>(&h0);
            st.y = *reinterpret_cast<unsigned int*>(&h1);
            *reinterpret_cast<uint2*>(sm.votes + i * VSH2 + oo * 8 + pr * 2) = st;
        }
    }
    __syncthreads();   // votes + rp ready

    // ---- EM mapping: warp=(o,h); lane=(c,pq); i=c+8*ii; p = 8h+2pq,+1 ----
    const int lane = tid & 31;
    const int wid  = tid >> 5;
    const int o    = wid & 15;
    const int h    = wid >> 4;
    const int pq   = lane & 3;
    const int c    = lane >> 2;
    const float bv = beta_v[o];

    // strip load: votes -> registers (conflict-free LDS.32: banks 8c+pq)
    __half2 vh[18];
    {
        const __half2* vb = sm.votes + o * 8 + 4 * h + pq;
        #pragma unroll
        for (int ii = 0; ii < 18; ++ii)
            vh[ii] = vb[(c + (ii << 3)) * VSH2];
    }
    const float* rpo = sm.rpT + o * RST;

    for (int it = 0; it < 3; ++it) {
        // ---- M-step: single-pass moments (votes in regs, rp broadcast LDS) ----
        float m0=0.f,m1=0.f,s0=0.f,s1=0.f,rs=0.f;
        #pragma unroll
        for (int ii = 0; ii < 18; ++ii) {
            float rp = rpo[c + (ii << 3)];
            float2 f = __half22float2(vh[ii]);
            float tx = rp * f.x, ty = rp * f.y;
            m0 += tx;  s0 = fmaf(tx, f.x, s0);
            m1 += ty;  s1 = fmaf(ty, f.y, s1);
            rs += rp;
        }
        #pragma unroll
        for (int off = 4; off < 32; off <<= 1) {   // reduce over c
            m0 += __shfl_xor_sync(0xffffffffu, m0, off);
            m1 += __shfl_xor_sync(0xffffffffu, m1, off);
            s0 += __shfl_xor_sync(0xffffffffu, s0, off);
            s1 += __shfl_xor_sync(0xffffffffu, s1, off);
            rs += __shfl_xor_sync(0xffffffffu, rs, off);
        }
        const float inv_r = __fdividef(1.0f, rs + EPSF);
        const float me0 = m0 * inv_r, me1 = m1 * inv_r;
        float e0 = fmaf(me0, fmaf(me0, rs, -2.0f * m0), s0);
        float e1 = fmaf(me1, fmaf(me1, rs, -2.0f * m1), s1);
        float v0 = fmaxf(e0, 0.f) * inv_r, v1 = fmaxf(e1, 0.f) * inv_r;
        float l2 = __logf(sqrtf(v0) + EPSF) + __logf(sqrtf(v1) + EPSF);
        l2 += __shfl_xor_sync(0xffffffffu, l2, 1);
        l2 += __shfl_xor_sync(0xffffffffu, l2, 2);   // 8-p partial (this h)

        if (it == 2) {
            if (c == 0) {   // pose out: p = 8h+2pq, +1
                *reinterpret_cast<float2*>(out + n * 256 + o * 16 + 8 * h + 2 * pq) =
                    make_float2(me0, me1);
            }
            if (lane == 0) {
                sm.l8S[h][o] = l2;
                if (h == 0) sm.rsS[o] = rs;
            }
            __syncthreads();
            if (tid < OSZ) {
                float lsum = sm.l8S[0][tid] + sm.l8S[1][tid];
                float cost = fmaf(16.0f, beta_v[tid], lsum) * sm.rsS[tid];
                float a = __fdividef(1.0f, 1.0f + __expf(-3.0f * (beta_a[tid] - cost)));
                out[NPOS * 256 + n * OSZ + tid] = a;
            }
            return;
        }

        const float iv0 = __fdividef(1.0f, 2.0f * v0 + EPSF);
        const float iv1 = __fdividef(1.0f, 2.0f * v1 + EPSF);
        if (lane == 0) {
            sm.l8S[h][o] = l2;
            if (h == 0) sm.rsS[o] = rs;
        }

        // ---- E-step part 1: 8-p distance partials from registers ----
        #pragma unroll
        for (int ii = 0; ii < 18; ++ii) {
            float2 f = __half22float2(vh[ii]);
            float dx = f.x - me0, dy = f.y - me1;
            float acc = fmaf(dy * dy, iv1, dx * dx * iv0);
            acc += __shfl_xor_sync(0xffffffffu, acc, 1);
            acc += __shfl_xor_sync(0xffffffffu, acc, 2);   // sum over 8 p (this h)
            if (pq == 0)
                sm.zpart[h][o * RST + c + (ii << 3)] = acc;
        }
        __syncthreads();   // zpart + l8S + rsS ready

        // per-o constant: czS = log(a)+0 - lsum
        if (tid < OSZ) {
            float lsum = sm.l8S[0][tid] + sm.l8S[1][tid];
            float cost = fmaf(16.0f, beta_v[tid], lsum) * sm.rsS[tid];
            float inv_temp = 1.0f + (float)it;
            float a = __fdividef(1.0f, 1.0f + __expf(-inv_temp * (beta_a[tid] - cost)));
            sm.czS[tid] = __logf(a + EPSF) - lsum;
        }
        __syncthreads();   // czS ready

        // ---- E-step part 2: softmax over o, fold act -> rp ----
        if (tid < 2 * ISZ) {
            const int i  = tid >> 1;
            const int g2 = tid & 1;
            float zz[8];
            float zmax = -1e30f;
            #pragma unroll
            for (int j = 0; j < 8; ++j) {
                int oo = (j << 1) + g2;
                float dist = sm.zpart[0][oo * RST + i] + sm.zpart[1][oo * RST + i];
                float z = sm.czS[oo] - dist;
                zz[j] = z;
                zmax = fmaxf(zmax, z);
            }
            zmax = fmaxf(zmax, __shfl_xor_sync(0xffffffffu, zmax, 1));
            float es = 0.f;
            #pragma unroll
            for (int j = 0; j < 8; ++j) { zz[j] = __expf(zz[j] - zmax); es += zz[j]; }
            es += __shfl_xor_sync(0xffffffffu, es, 1);
            const float f = __fdividef(sm.actS[i], es);   // softmax * act
            #pragma unroll
            for (int j = 0; j < 8; ++j)
                sm.rpT[((j << 1) + g2) * RST + i] = zz[j] * f;
        }
        __syncthreads();   // rp ready for next M-step
    }
}

extern "C" void kernel_launch(void* const* d_in, const int* in_sizes, int n_in,
                              void* d_out, int out_size)
{
    const float* pose_in = (const float*)d_in[0];
    const float* act_in  = (const float*)d_in[1];
    const float* w       = (const float*)d_in[2];
    const float* bv      = (const float*)d_in[3];
    const float* ba      = (const float*)d_in[4];
    float* out           = (float*)d_out;

    const int smem = (int)sizeof(Smem);
    cudaFuncSetAttribute(capsconv_em_kernel,
                         cudaFuncAttributeMaxDynamicSharedMemorySize, smem);
    capsconv_em_kernel<<<NPOS, 1024, smem>>>(pose_in, act_in, w, bv, ba, out);
}